// round 14
// baseline (speedup 1.0000x reference)
#include <cuda_runtime.h>
#include <cuda_fp16.h>
#include <cstdint>

#define C 128
#define MAXN 100000
#define MAXE 1600000
#define LN_EPS 1e-5f

// Scratch (allocation-free rule: __device__ globals; BSS zero-initialized.
// Invariants at kernel_launch entry (restored every replay):
//   g_cursor all-zero   (k_agg tail re-zeros)
//   g_scanstate all-zero (ln_hist block 0 re-zeros; graph-ordered before scan)
__device__ __half    g_hh[MAXN * 128];     // h fp16 [N,128]
__device__ __half    g_meanh[MAXN * 128];  // mean fp16 [N,128]
__device__ int       g_rowstart[MAXN + 1]; // CSR row offsets (by dst)
__device__ int       g_cursor[MAXN];       // counts -> offsets -> fill cursor
__device__ int       g_csr[MAXE];          // src ids grouped by dst
__device__ unsigned  g_scanstate[128];     // per-chunk published totals (+1)

// ===========================================================================
// Inline edge-dtype detection: 32 int64 samples all in [0,N) => int64.
// ===========================================================================
__device__ __forceinline__ bool is_i64(const void* ei_, int N, int E) {
    int lane = threadIdx.x & 31;
    int n = E < 32 ? E : 32;
    long long v = ((const long long*)ei_)[lane % n];
    bool ok = (v >= 0 && v < (long long)N);
    return __all_sync(0xffffffffu, ok);
}

// ===========================================================================
// K0: MERGED LayerNorm+ReLU (blocks [0, lnblocks)) and dst-degree histogram.
// Block 0 also re-zeros g_scanstate for this replay's scan.
// ===========================================================================
__global__ void k_ln_hist(const float* __restrict__ x,
                          const float* __restrict__ gamma,
                          const float* __restrict__ beta,
                          const void* ei_, int N, int E, int lnblocks) {
    if (blockIdx.x == 0 && threadIdx.x < 128) g_scanstate[threadIdx.x] = 0u;

    if ((int)blockIdx.x < lnblocks) {
        int w    = (blockIdx.x * blockDim.x + threadIdx.x) >> 5;
        int lane = threadIdx.x & 31;
        if (w >= N) return;

        float4 v = ((const float4*)x)[(size_t)w * 32 + lane];
        float s  = v.x + v.y + v.z + v.w;
        float sq = v.x * v.x + v.y * v.y + v.z * v.z + v.w * v.w;
#pragma unroll
        for (int o = 16; o; o >>= 1) {
            s  += __shfl_xor_sync(0xffffffffu, s, o);
            sq += __shfl_xor_sync(0xffffffffu, sq, o);
        }
        float mu  = s * (1.0f / C);
        float var = sq * (1.0f / C) - mu * mu;
        float rs  = rsqrtf(var + LN_EPS);

        float4 g = ((const float4*)gamma)[lane];
        float4 b = ((const float4*)beta)[lane];
        float hx = fmaxf(0.0f, (v.x - mu) * rs * g.x + b.x);
        float hy = fmaxf(0.0f, (v.y - mu) * rs * g.y + b.y);
        float hz = fmaxf(0.0f, (v.z - mu) * rs * g.z + b.z);
        float hw = fmaxf(0.0f, (v.w - mu) * rs * g.w + b.w);

        __half2 p0 = __floats2half2_rn(hx, hy);
        __half2 p1 = __floats2half2_rn(hz, hw);
        uint2 pk = make_uint2(*(uint32_t*)&p0, *(uint32_t*)&p1);
        ((uint2*)g_hh)[(size_t)w * 32 + lane] = pk;
    } else {
        bool i64 = is_i64(ei_, N, E);
        int e = (blockIdx.x - lnblocks) * blockDim.x + threadIdx.x;
        if (e >= E) return;
        int d = i64 ? (int)((const long long*)ei_)[(size_t)E + e]
                    : ((const int*)ei_)[(size_t)E + e];
        atomicAdd(&g_cursor[d], 1);
    }
}

// ===========================================================================
// K1: single-pass exclusive scan (publish chunk total, gather predecessors).
// ===========================================================================
__global__ void k_scan(int N, int nb) {
    __shared__ int wsum[8];
    __shared__ int s_ex;
    int b = blockIdx.x, t = threadIdx.x;
    int lane = t & 31, wid = t >> 5;
    int idx0 = b * 1024 + t * 4;

    int c[4];
#pragma unroll
    for (int k = 0; k < 4; ++k)
        c[k] = (idx0 + k < N) ? g_cursor[idx0 + k] : 0;
    int tsum = c[0] + c[1] + c[2] + c[3];

    int v = tsum;
#pragma unroll
    for (int o = 1; o < 32; o <<= 1) {
        int xx = __shfl_up_sync(0xffffffffu, v, o);
        if (lane >= o) v += xx;
    }
    if (lane == 31) wsum[wid] = v;
    __syncthreads();

    if (t == 0) {
        int run = 0;
#pragma unroll
        for (int i = 0; i < 8; ++i) { int w = wsum[i]; wsum[i] = run; run += w; }
        atomicExch(&g_scanstate[b], (unsigned)(run + 1));  // publish (+1)
    }
    __syncthreads();

    if (wid == 0) {
        int ex = 0;
        for (int w0 = 0; w0 < b; w0 += 32) {
            int j = w0 + lane;
            int val = 0;
            if (j < b) {
                unsigned st;
                while ((st = atomicAdd(&g_scanstate[j], 0u)) == 0u)
                    __nanosleep(64);
                val = (int)st - 1;
            }
#pragma unroll
            for (int o = 16; o; o >>= 1)
                val += __shfl_xor_sync(0xffffffffu, val, o);
            ex += val;
        }
        if (lane == 0) s_ex = ex;
    }
    __syncthreads();

    int texcl = (v - tsum) + wsum[wid];
    int run = s_ex + texcl;
#pragma unroll
    for (int k = 0; k < 4; ++k) {
        int idx = idx0 + k;
        if (idx < N) {
            g_rowstart[idx] = run;
            g_cursor[idx]   = run;
            run += c[k];
            if (idx == N - 1) g_rowstart[N] = run;
        }
    }
}

// ===========================================================================
// K2: fill CSR src lists (2 edges per thread, vectorized loads)
// ===========================================================================
__global__ void k_fill(const void* ei_, int N, int E) {
    bool i64 = is_i64(ei_, N, E);
    int e0 = (blockIdx.x * blockDim.x + threadIdx.x) * 2;
    if (e0 >= E) return;
    if (i64) {
        const long long* ei = (const long long*)ei_;
        if (e0 + 1 < E) {
            longlong2 sp = *(const longlong2*)(ei + e0);
            longlong2 dp = *(const longlong2*)(ei + E + e0);
            int p0 = atomicAdd(&g_cursor[(int)dp.x], 1);
            int p1 = atomicAdd(&g_cursor[(int)dp.y], 1);
            g_csr[p0] = (int)sp.x;
            g_csr[p1] = (int)sp.y;
        } else {
            int s = (int)ei[e0], d = (int)ei[(size_t)E + e0];
            g_csr[atomicAdd(&g_cursor[d], 1)] = s;
        }
    } else {
        const int* ei = (const int*)ei_;
        if (e0 + 1 < E) {
            int2 sp = *(const int2*)(ei + e0);
            int2 dp = *(const int2*)(ei + E + e0);
            int p0 = atomicAdd(&g_cursor[dp.x], 1);
            int p1 = atomicAdd(&g_cursor[dp.y], 1);
            g_csr[p0] = sp.x;
            g_csr[p1] = sp.y;
        } else {
            int s = ei[e0], d = ei[(size_t)E + e0];
            g_csr[atomicAdd(&g_cursor[d], 1)] = s;
        }
    }
}

// ===========================================================================
// K3: gather-sum aggregation, one warp per dst node.
// R14: rotated half2 accumulators — per neighbor SHFL + LDG.64 + 2 HADD2
// into acc[j&3] (8 independent chains, adds 4 iterations apart -> latency
// hidden), flushed to fp32 once per 32-edge chunk. Same traffic as R11,
// ~40% fewer issue slots, no serial-chain hazard (R12's failure mode).
// Tail: re-zero g_cursor to restore the entry invariant for the next replay.
// ===========================================================================
__global__ void k_agg(int N) {
    int w    = (blockIdx.x * blockDim.x + threadIdx.x) >> 5;
    int lane = threadIdx.x & 31;
    if (w >= N) return;

    int start = g_rowstart[w];
    int end   = g_rowstart[w + 1];
    int deg   = end - start;

    float4 acc = make_float4(0.f, 0.f, 0.f, 0.f);
    const uint2* hh = (const uint2*)g_hh;
    for (int base = start; base < end; base += 32) {
        int m = end - base; if (m > 32) m = 32;
        int s = (lane < m) ? g_csr[base + lane] : 0;

        __half2 ha[4], hb[4];
#pragma unroll
        for (int r = 0; r < 4; ++r) {
            ha[r] = __float2half2_rn(0.f);
            hb[r] = __float2half2_rn(0.f);
        }
#pragma unroll 8
        for (int j = 0; j < 32; ++j) {
            if (j >= m) break;
            int sj = __shfl_sync(0xffffffffu, s, j);
            uint2 pk = hh[(size_t)sj * 32 + lane];
            int r = j & 3;
            ha[r] = __hadd2(ha[r], *(__half2*)&pk.x);
            hb[r] = __hadd2(hb[r], *(__half2*)&pk.y);
        }
#pragma unroll
        for (int r = 0; r < 4; ++r) {
            float2 f0 = __half22float2(ha[r]);
            float2 f1 = __half22float2(hb[r]);
            acc.x += f0.x; acc.y += f0.y; acc.z += f1.x; acc.w += f1.y;
        }
    }
    float inv = deg > 0 ? 1.0f / (float)deg : 0.0f;
    __half2 p0 = __floats2half2_rn(acc.x * inv, acc.y * inv);
    __half2 p1 = __floats2half2_rn(acc.z * inv, acc.w * inv);
    ((uint2*)g_meanh)[(size_t)w * 32 + lane] =
        make_uint2(*(uint32_t*)&p0, *(uint32_t*)&p1);

    if (lane == 0) g_cursor[w] = 0;   // restore invariant for next replay
}

// ===========================================================================
// fp16 mma helper (m16n8k16, fp32 accumulate — plain sm_103 PTX, sm_80+)
// ===========================================================================
__device__ __forceinline__ void mma_f16(float4& d,
                                        uint32_t a0, uint32_t a1,
                                        uint32_t a2, uint32_t a3,
                                        uint32_t b0, uint32_t b1) {
    asm volatile(
        "mma.sync.aligned.m16n8k16.row.col.f32.f16.f16.f32 "
        "{%0,%1,%2,%3}, {%4,%5,%6,%7}, {%8,%9}, {%0,%1,%2,%3};"
        : "+f"(d.x), "+f"(d.y), "+f"(d.z), "+f"(d.w)
        : "r"(a0), "r"(a1), "r"(a2), "r"(a3), "r"(b0), "r"(b1));
}

// ===========================================================================
// K4: fp16 tensor-core GEMM epilogue via mma.sync m16n8k16.
//   out[128-row tile, 128] = mean @ Wl^T + h @ Wr^T + bias + x
// ~103KB SMEM -> 2 CTAs/SM.
// ===========================================================================
#define BPITCH_H 264
#define APITCH_H 136
#define OFFH_B   0
#define OFFH_A   (128 * BPITCH_H)               // halves
#define OFFH_BI  (OFFH_A + 128 * APITCH_H)      // halves (bias fp32 region)
#define SMEM_HALVES (OFFH_BI + 256)
#define SMEM_TOT (SMEM_HALVES * 2)

__global__ void __launch_bounds__(256, 2)
k_gemm_mma(const float* __restrict__ x,
           const float* __restrict__ Wl,
           const float* __restrict__ bl,
           const float* __restrict__ Wr,
           float* __restrict__ out, int N, int ntiles) {
    extern __shared__ __half smemh[];
    __half* sB  = smemh + OFFH_B;
    __half* sA  = smemh + OFFH_A;
    float*  sbi = (float*)(smemh + OFFH_BI);

    int tid  = threadIdx.x;
    int wid  = tid >> 5;
    int lane = tid & 31;
    int ly   = lane >> 2;   // groupID 0..7
    int lx   = lane & 3;    // threadID_in_group 0..3

    for (int i = tid; i < 128 * 128; i += 256) {
        int n = i >> 7, k = i & 127;
        sB[n * BPITCH_H + k]       = __float2half(Wl[i]);
        sB[n * BPITCH_H + 128 + k] = __float2half(Wr[i]);
    }
    for (int i = tid; i < 128; i += 256) sbi[i] = bl[i];
    __syncthreads();

    const uint4* meanp = (const uint4*)g_meanh;
    const uint4* hp    = (const uint4*)g_hh;
    const uint32_t* sAu = (const uint32_t*)sA;
    const uint32_t* sBu = (const uint32_t*)sB;
    uint4* sA4 = (uint4*)sA;

    int rb = wid * 16;

    for (int t = blockIdx.x; t < ntiles; t += gridDim.x) {
        int rbase = t * 128;
        float4 acc[16];
#pragma unroll
        for (int nt = 0; nt < 16; ++nt) acc[nt] = make_float4(0.f, 0.f, 0.f, 0.f);

#pragma unroll
        for (int half = 0; half < 2; ++half) {
            const uint4* src = half ? hp : meanp;
            for (int i = tid; i < 128 * 16; i += 256) {
                int r = i >> 4, c8 = i & 15;
                int row = rbase + r;
                uint4 pk = (row < N) ? src[(size_t)row * 16 + c8]
                                     : make_uint4(0u, 0u, 0u, 0u);
                sA4[r * 17 + c8] = pk;
            }
            __syncthreads();

            int kbase2 = half * 64;
#pragma unroll
            for (int ks = 0; ks < 8; ++ks) {
                int kl2 = ks * 8;
                uint32_t a0 = sAu[(rb + ly)     * (APITCH_H / 2) + kl2 + lx];
                uint32_t a1 = sAu[(rb + ly + 8) * (APITCH_H / 2) + kl2 + lx];
                uint32_t a2 = sAu[(rb + ly)     * (APITCH_H / 2) + kl2 + lx + 4];
                uint32_t a3 = sAu[(rb + ly + 8) * (APITCH_H / 2) + kl2 + lx + 4];
#pragma unroll
                for (int nt = 0; nt < 16; ++nt) {
                    int nrow = nt * 8 + ly;
                    uint32_t b0 = sBu[nrow * (BPITCH_H / 2) + kbase2 + kl2 + lx];
                    uint32_t b1 = sBu[nrow * (BPITCH_H / 2) + kbase2 + kl2 + lx + 4];
                    mma_f16(acc[nt], a0, a1, a2, a3, b0, b1);
                }
            }
            __syncthreads();
        }

        int row0 = rbase + rb + ly;
        int row1 = row0 + 8;
#pragma unroll
        for (int nt = 0; nt < 16; ++nt) {
            int col = nt * 8 + lx * 2;
            float2 bv = *(const float2*)(sbi + col);
            if (row0 < N) {
                float2 xv = ((const float2*)x)[(size_t)row0 * 64 + (col >> 1)];
                float2 o = make_float2(acc[nt].x + bv.x + xv.x,
                                       acc[nt].y + bv.y + xv.y);
                ((float2*)out)[(size_t)row0 * 64 + (col >> 1)] = o;
            }
            if (row1 < N) {
                float2 xv = ((const float2*)x)[(size_t)row1 * 64 + (col >> 1)];
                float2 o = make_float2(acc[nt].z + bv.x + xv.x,
                                       acc[nt].w + bv.y + xv.y);
                ((float2*)out)[(size_t)row1 * 64 + (col >> 1)] = o;
            }
        }
    }
}

// ===========================================================================
extern "C" void kernel_launch(void* const* d_in, const int* in_sizes, int n_in,
                              void* d_out, int out_size) {
    const float* x     = (const float*)d_in[0];
    const void*  ei    = d_in[1];
    const float* gamma = (const float*)d_in[2];
    const float* beta  = (const float*)d_in[3];
    const float* Wl    = (const float*)d_in[4];
    const float* bl    = (const float*)d_in[5];
    const float* Wr    = (const float*)d_in[6];
    float*       out   = (float*)d_out;

    int N = in_sizes[0] / C;       // 100000
    int E = in_sizes[1] / 2;       // 1600000
    int nb = (N + 1023) / 1024;    // 98 — co-resident, single-pass scan OK
    int ntiles = (N + 127) / 128;

    int lnblocks   = (N + 7) / 8;            // 12500
    int histblocks = (E + 255) / 256;        // 6250

    k_ln_hist<<<lnblocks + histblocks, 256>>>(x, gamma, beta, ei, N, E, lnblocks); // 0
    k_scan<<<nb, 256>>>(N, nb);                                                    // 1
    k_fill<<<(E / 2 + 255) / 256, 256>>>(ei, N, E);                                // 2
    k_agg<<<(N + 7) / 8, 256>>>(N);                                                // 3 <- profiled
    cudaFuncSetAttribute(k_gemm_mma, cudaFuncAttributeMaxDynamicSharedMemorySize,
                         SMEM_TOT);
    int sms = 148;
    cudaDeviceGetAttribute(&sms, cudaDevAttrMultiProcessorCount, 0);
    int grid = 2 * sms < ntiles ? 2 * sms : ntiles;
    k_gemm_mma<<<grid, 256, SMEM_TOT>>>(x, Wl, bl, Wr, out, N, ntiles);            // 4
}

// round 15
// speedup vs baseline: 1.1665x; 1.1665x over previous
#include <cuda_runtime.h>
#include <cuda_fp16.h>
#include <cstdint>

#define C 128
#define MAXN 100000
#define MAXE 1600000
#define LN_EPS 1e-5f

// Scratch (allocation-free rule: __device__ globals; BSS zero-initialized.
// Invariants at kernel_launch entry (restored every replay):
//   g_cursor all-zero   (k_agg tail re-zeros)
//   g_scanstate all-zero (k_hist block 0 re-zeros; graph-ordered before scan)
__device__ __half    g_hh[MAXN * 128];     // h fp16 [N,128]
__device__ __half    g_meanh[MAXN * 128];  // mean fp16 [N,128]
__device__ int       g_rowstart[MAXN + 1]; // CSR row offsets (by dst)
__device__ int       g_cursor[MAXN];       // counts -> offsets -> fill cursor
__device__ int       g_csr[MAXE];          // src ids grouped by dst
__device__ unsigned  g_scanstate[128];     // per-chunk published totals (+1)

// ===========================================================================
// Inline edge-dtype detection: 32 int64 samples all in [0,N) => int64.
// ===========================================================================
__device__ __forceinline__ bool is_i64(const void* ei_, int N, int E) {
    int lane = threadIdx.x & 31;
    int n = E < 32 ? E : 32;
    long long v = ((const long long*)ei_)[lane % n];
    bool ok = (v >= 0 && v < (long long)N);
    return __all_sync(0xffffffffu, ok);
}

// ===========================================================================
// K0: dst-degree histogram. Block 0 also re-zeros g_scanstate.
// ===========================================================================
__global__ void k_hist(const void* ei_, int N, int E) {
    if (blockIdx.x == 0 && threadIdx.x < 128) g_scanstate[threadIdx.x] = 0u;
    bool i64 = is_i64(ei_, N, E);
    int e = blockIdx.x * blockDim.x + threadIdx.x;
    if (e >= E) return;
    int d = i64 ? (int)((const long long*)ei_)[(size_t)E + e]
                : ((const int*)ei_)[(size_t)E + e];
    atomicAdd(&g_cursor[d], 1);
}

// ===========================================================================
// K1: single-pass exclusive scan (publish chunk total, gather predecessors).
// All nb<=128 blocks co-resident (nb=98 < 148 SMs) => spin-gather is safe.
// ===========================================================================
__global__ void k_scan(int N, int nb) {
    __shared__ int wsum[8];
    __shared__ int s_ex;
    int b = blockIdx.x, t = threadIdx.x;
    int lane = t & 31, wid = t >> 5;
    int idx0 = b * 1024 + t * 4;

    int c[4];
#pragma unroll
    for (int k = 0; k < 4; ++k)
        c[k] = (idx0 + k < N) ? g_cursor[idx0 + k] : 0;
    int tsum = c[0] + c[1] + c[2] + c[3];

    int v = tsum;
#pragma unroll
    for (int o = 1; o < 32; o <<= 1) {
        int xx = __shfl_up_sync(0xffffffffu, v, o);
        if (lane >= o) v += xx;
    }
    if (lane == 31) wsum[wid] = v;
    __syncthreads();

    if (t == 0) {
        int run = 0;
#pragma unroll
        for (int i = 0; i < 8; ++i) { int w = wsum[i]; wsum[i] = run; run += w; }
        atomicExch(&g_scanstate[b], (unsigned)(run + 1));  // publish (+1)
    }
    __syncthreads();

    if (wid == 0) {
        int ex = 0;
        for (int w0 = 0; w0 < b; w0 += 32) {
            int j = w0 + lane;
            int val = 0;
            if (j < b) {
                unsigned st;
                while ((st = atomicAdd(&g_scanstate[j], 0u)) == 0u)
                    __nanosleep(64);
                val = (int)st - 1;
            }
#pragma unroll
            for (int o = 16; o; o >>= 1)
                val += __shfl_xor_sync(0xffffffffu, val, o);
            ex += val;
        }
        if (lane == 0) s_ex = ex;
    }
    __syncthreads();

    int texcl = (v - tsum) + wsum[wid];
    int run = s_ex + texcl;
#pragma unroll
    for (int k = 0; k < 4; ++k) {
        int idx = idx0 + k;
        if (idx < N) {
            g_rowstart[idx] = run;
            g_cursor[idx]   = run;
            run += c[k];
            if (idx == N - 1) g_rowstart[N] = run;
        }
    }
}

// ===========================================================================
// K2: MERGED LayerNorm+ReLU (blocks [0, lnblocks)) and CSR fill (rest).
// fill is latency-bound (measured issue=3.4%) -> LN's DRAM work executes
// inside fill's latency bubbles nearly for free.
// ===========================================================================
__global__ void k_ln_fill(const float* __restrict__ x,
                          const float* __restrict__ gamma,
                          const float* __restrict__ beta,
                          const void* ei_, int N, int E, int lnblocks) {
    if ((int)blockIdx.x < lnblocks) {
        int w    = (blockIdx.x * blockDim.x + threadIdx.x) >> 5;
        int lane = threadIdx.x & 31;
        if (w >= N) return;

        float4 v = ((const float4*)x)[(size_t)w * 32 + lane];
        float s  = v.x + v.y + v.z + v.w;
        float sq = v.x * v.x + v.y * v.y + v.z * v.z + v.w * v.w;
#pragma unroll
        for (int o = 16; o; o >>= 1) {
            s  += __shfl_xor_sync(0xffffffffu, s, o);
            sq += __shfl_xor_sync(0xffffffffu, sq, o);
        }
        float mu  = s * (1.0f / C);
        float var = sq * (1.0f / C) - mu * mu;
        float rs  = rsqrtf(var + LN_EPS);

        float4 g = ((const float4*)gamma)[lane];
        float4 b = ((const float4*)beta)[lane];
        float hx = fmaxf(0.0f, (v.x - mu) * rs * g.x + b.x);
        float hy = fmaxf(0.0f, (v.y - mu) * rs * g.y + b.y);
        float hz = fmaxf(0.0f, (v.z - mu) * rs * g.z + b.z);
        float hw = fmaxf(0.0f, (v.w - mu) * rs * g.w + b.w);

        __half2 p0 = __floats2half2_rn(hx, hy);
        __half2 p1 = __floats2half2_rn(hz, hw);
        uint2 pk = make_uint2(*(uint32_t*)&p0, *(uint32_t*)&p1);
        ((uint2*)g_hh)[(size_t)w * 32 + lane] = pk;
    } else {
        bool i64 = is_i64(ei_, N, E);
        int e0 = ((blockIdx.x - lnblocks) * blockDim.x + threadIdx.x) * 2;
        if (e0 >= E) return;
        if (i64) {
            const long long* ei = (const long long*)ei_;
            if (e0 + 1 < E) {
                longlong2 sp = *(const longlong2*)(ei + e0);
                longlong2 dp = *(const longlong2*)(ei + E + e0);
                int p0 = atomicAdd(&g_cursor[(int)dp.x], 1);
                int p1 = atomicAdd(&g_cursor[(int)dp.y], 1);
                g_csr[p0] = (int)sp.x;
                g_csr[p1] = (int)sp.y;
            } else {
                int s = (int)ei[e0], d = (int)ei[(size_t)E + e0];
                g_csr[atomicAdd(&g_cursor[d], 1)] = s;
            }
        } else {
            const int* ei = (const int*)ei_;
            if (e0 + 1 < E) {
                int2 sp = *(const int2*)(ei + e0);
                int2 dp = *(const int2*)(ei + E + e0);
                int p0 = atomicAdd(&g_cursor[dp.x], 1);
                int p1 = atomicAdd(&g_cursor[dp.y], 1);
                g_csr[p0] = sp.x;
                g_csr[p1] = sp.y;
            } else {
                int s = ei[e0], d = ei[(size_t)E + e0];
                g_csr[atomicAdd(&g_cursor[d], 1)] = s;
            }
        }
    }
}

// ===========================================================================
// K3: gather-sum aggregation, one warp per dst node (EXACT R11 version:
// 49us, 32 regs, 80% occ — proven optimum after 3 failed variants).
// Tail: re-zero g_cursor to restore the entry invariant for the next replay.
// ===========================================================================
__global__ void k_agg(int N) {
    int w    = (blockIdx.x * blockDim.x + threadIdx.x) >> 5;
    int lane = threadIdx.x & 31;
    if (w >= N) return;

    int start = g_rowstart[w];
    int end   = g_rowstart[w + 1];
    int deg   = end - start;

    float4 acc = make_float4(0.f, 0.f, 0.f, 0.f);
    const uint2* hh = (const uint2*)g_hh;
    for (int base = start; base < end; base += 32) {
        int m = end - base; if (m > 32) m = 32;
        int s = (lane < m) ? g_csr[base + lane] : 0;
#pragma unroll 8
        for (int j = 0; j < 32; ++j) {
            if (j >= m) break;
            int sj = __shfl_sync(0xffffffffu, s, j);
            uint2 pk = hh[(size_t)sj * 32 + lane];
            float2 f0 = __half22float2(*(__half2*)&pk.x);
            float2 f1 = __half22float2(*(__half2*)&pk.y);
            acc.x += f0.x; acc.y += f0.y; acc.z += f1.x; acc.w += f1.y;
        }
    }
    float inv = deg > 0 ? 1.0f / (float)deg : 0.0f;
    __half2 p0 = __floats2half2_rn(acc.x * inv, acc.y * inv);
    __half2 p1 = __floats2half2_rn(acc.z * inv, acc.w * inv);
    ((uint2*)g_meanh)[(size_t)w * 32 + lane] =
        make_uint2(*(uint32_t*)&p0, *(uint32_t*)&p1);

    if (lane == 0) g_cursor[w] = 0;   // restore invariant for next replay
}

// ===========================================================================
// fp16 mma helper (m16n8k16, fp32 accumulate — plain sm_103 PTX, sm_80+)
// ===========================================================================
__device__ __forceinline__ void mma_f16(float4& d,
                                        uint32_t a0, uint32_t a1,
                                        uint32_t a2, uint32_t a3,
                                        uint32_t b0, uint32_t b1) {
    asm volatile(
        "mma.sync.aligned.m16n8k16.row.col.f32.f16.f16.f32 "
        "{%0,%1,%2,%3}, {%4,%5,%6,%7}, {%8,%9}, {%0,%1,%2,%3};"
        : "+f"(d.x), "+f"(d.y), "+f"(d.z), "+f"(d.w)
        : "r"(a0), "r"(a1), "r"(a2), "r"(a3), "r"(b0), "r"(b1));
}

// ===========================================================================
// K4: fp16 tensor-core GEMM epilogue via mma.sync m16n8k16 (EXACT R10/R11).
//   out[128-row tile, 128] = mean @ Wl^T + h @ Wr^T + bias + x
// ~103KB SMEM -> 2 CTAs/SM.
// ===========================================================================
#define BPITCH_H 264
#define APITCH_H 136
#define OFFH_B   0
#define OFFH_A   (128 * BPITCH_H)               // halves
#define OFFH_BI  (OFFH_A + 128 * APITCH_H)      // halves (bias fp32 region)
#define SMEM_HALVES (OFFH_BI + 256)
#define SMEM_TOT (SMEM_HALVES * 2)

__global__ void __launch_bounds__(256, 2)
k_gemm_mma(const float* __restrict__ x,
           const float* __restrict__ Wl,
           const float* __restrict__ bl,
           const float* __restrict__ Wr,
           float* __restrict__ out, int N, int ntiles) {
    extern __shared__ __half smemh[];
    __half* sB  = smemh + OFFH_B;
    __half* sA  = smemh + OFFH_A;
    float*  sbi = (float*)(smemh + OFFH_BI);

    int tid  = threadIdx.x;
    int wid  = tid >> 5;
    int lane = tid & 31;
    int ly   = lane >> 2;   // groupID 0..7
    int lx   = lane & 3;    // threadID_in_group 0..3

    for (int i = tid; i < 128 * 128; i += 256) {
        int n = i >> 7, k = i & 127;
        sB[n * BPITCH_H + k]       = __float2half(Wl[i]);
        sB[n * BPITCH_H + 128 + k] = __float2half(Wr[i]);
    }
    for (int i = tid; i < 128; i += 256) sbi[i] = bl[i];
    __syncthreads();

    const uint4* meanp = (const uint4*)g_meanh;
    const uint4* hp    = (const uint4*)g_hh;
    const uint32_t* sAu = (const uint32_t*)sA;
    const uint32_t* sBu = (const uint32_t*)sB;
    uint4* sA4 = (uint4*)sA;

    int rb = wid * 16;

    for (int t = blockIdx.x; t < ntiles; t += gridDim.x) {
        int rbase = t * 128;
        float4 acc[16];
#pragma unroll
        for (int nt = 0; nt < 16; ++nt) acc[nt] = make_float4(0.f, 0.f, 0.f, 0.f);

#pragma unroll
        for (int half = 0; half < 2; ++half) {
            const uint4* src = half ? hp : meanp;
            for (int i = tid; i < 128 * 16; i += 256) {
                int r = i >> 4, c8 = i & 15;
                int row = rbase + r;
                uint4 pk = (row < N) ? src[(size_t)row * 16 + c8]
                                     : make_uint4(0u, 0u, 0u, 0u);
                sA4[r * 17 + c8] = pk;
            }
            __syncthreads();

            int kbase2 = half * 64;
#pragma unroll
            for (int ks = 0; ks < 8; ++ks) {
                int kl2 = ks * 8;
                uint32_t a0 = sAu[(rb + ly)     * (APITCH_H / 2) + kl2 + lx];
                uint32_t a1 = sAu[(rb + ly + 8) * (APITCH_H / 2) + kl2 + lx];
                uint32_t a2 = sAu[(rb + ly)     * (APITCH_H / 2) + kl2 + lx + 4];
                uint32_t a3 = sAu[(rb + ly + 8) * (APITCH_H / 2) + kl2 + lx + 4];
#pragma unroll
                for (int nt = 0; nt < 16; ++nt) {
                    int nrow = nt * 8 + ly;
                    uint32_t b0 = sBu[nrow * (BPITCH_H / 2) + kbase2 + kl2 + lx];
                    uint32_t b1 = sBu[nrow * (BPITCH_H / 2) + kbase2 + kl2 + lx + 4];
                    mma_f16(acc[nt], a0, a1, a2, a3, b0, b1);
                }
            }
            __syncthreads();
        }

        int row0 = rbase + rb + ly;
        int row1 = row0 + 8;
#pragma unroll
        for (int nt = 0; nt < 16; ++nt) {
            int col = nt * 8 + lx * 2;
            float2 bv = *(const float2*)(sbi + col);
            if (row0 < N) {
                float2 xv = ((const float2*)x)[(size_t)row0 * 64 + (col >> 1)];
                float2 o = make_float2(acc[nt].x + bv.x + xv.x,
                                       acc[nt].y + bv.y + xv.y);
                ((float2*)out)[(size_t)row0 * 64 + (col >> 1)] = o;
            }
            if (row1 < N) {
                float2 xv = ((const float2*)x)[(size_t)row1 * 64 + (col >> 1)];
                float2 o = make_float2(acc[nt].z + bv.x + xv.x,
                                       acc[nt].w + bv.y + xv.y);
                ((float2*)out)[(size_t)row1 * 64 + (col >> 1)] = o;
            }
        }
    }
}

// ===========================================================================
extern "C" void kernel_launch(void* const* d_in, const int* in_sizes, int n_in,
                              void* d_out, int out_size) {
    const float* x     = (const float*)d_in[0];
    const void*  ei    = d_in[1];
    const float* gamma = (const float*)d_in[2];
    const float* beta  = (const float*)d_in[3];
    const float* Wl    = (const float*)d_in[4];
    const float* bl    = (const float*)d_in[5];
    const float* Wr    = (const float*)d_in[6];
    float*       out   = (float*)d_out;

    int N = in_sizes[0] / C;       // 100000
    int E = in_sizes[1] / 2;       // 1600000
    int nb = (N + 1023) / 1024;    // 98 — co-resident, single-pass scan OK
    int ntiles = (N + 127) / 128;

    int lnblocks   = (N + 7) / 8;            // 12500
    int fillblocks = (E / 2 + 255) / 256;    // 3125

    k_hist<<<(E + 255) / 256, 256>>>(ei, N, E);                                    // 0
    k_scan<<<nb, 256>>>(N, nb);                                                    // 1
    k_ln_fill<<<lnblocks + fillblocks, 256>>>(x, gamma, beta, ei, N, E, lnblocks); // 2
    k_agg<<<(N + 7) / 8, 256>>>(N);                                                // 3 <- profiled
    cudaFuncSetAttribute(k_gemm_mma, cudaFuncAttributeMaxDynamicSharedMemorySize,
                         SMEM_TOT);
    int sms = 148;
    cudaDeviceGetAttribute(&sms, cudaDevAttrMultiProcessorCount, 0);
    int grid = 2 * sms < ntiles ? 2 * sms : ntiles;
    k_gemm_mma<<<grid, 256, SMEM_TOT>>>(x, Wl, bl, Wr, out, N, ntiles);            // 4
}

// round 16
// speedup vs baseline: 1.1816x; 1.0129x over previous
#include <cuda_runtime.h>
#include <cuda_fp16.h>
#include <cstdint>

#define C 128
#define MAXN 100000
#define MAXE 1600000
#define LN_EPS 1e-5f

// Scratch (allocation-free rule: __device__ globals; BSS zero-initialized.
// Invariants at kernel_launch entry (restored every replay):
//   g_cursor all-zero   (k_agg tail re-zeros)
//   g_scanstate all-zero (k_hist block 0 re-zeros; graph-ordered before scan)
__device__ __half    g_hh[MAXN * 128];     // h fp16 [N,128]
__device__ __half    g_meanh[MAXN * 128];  // mean fp16 [N,128]
__device__ int       g_rowstart[MAXN + 1]; // CSR row offsets (by dst)
__device__ int       g_cursor[MAXN];       // counts -> offsets -> fill cursor
__device__ int       g_csr[MAXE];          // src ids grouped by dst
__device__ unsigned  g_scanstate[128];     // per-chunk published totals (+1)

// ===========================================================================
// Inline edge-dtype detection: 32 int64 samples all in [0,N) => int64.
// ===========================================================================
__device__ __forceinline__ bool is_i64(const void* ei_, int N, int E) {
    int lane = threadIdx.x & 31;
    int n = E < 32 ? E : 32;
    long long v = ((const long long*)ei_)[lane % n];
    bool ok = (v >= 0 && v < (long long)N);
    return __all_sync(0xffffffffu, ok);
}

// ===========================================================================
// K0: dst-degree histogram. Block 0 also re-zeros g_scanstate.
// ===========================================================================
__global__ void k_hist(const void* ei_, int N, int E) {
    if (blockIdx.x == 0 && threadIdx.x < 128) g_scanstate[threadIdx.x] = 0u;
    bool i64 = is_i64(ei_, N, E);
    int e = blockIdx.x * blockDim.x + threadIdx.x;
    if (e >= E) return;
    int d = i64 ? (int)((const long long*)ei_)[(size_t)E + e]
                : ((const int*)ei_)[(size_t)E + e];
    atomicAdd(&g_cursor[d], 1);
}

// ===========================================================================
// K1: single-pass exclusive scan (publish chunk total, gather predecessors).
// All nb<=128 blocks co-resident (nb=98 < 148 SMs) => spin-gather is safe.
// ===========================================================================
__global__ void k_scan(int N, int nb) {
    __shared__ int wsum[8];
    __shared__ int s_ex;
    int b = blockIdx.x, t = threadIdx.x;
    int lane = t & 31, wid = t >> 5;
    int idx0 = b * 1024 + t * 4;

    int c[4];
#pragma unroll
    for (int k = 0; k < 4; ++k)
        c[k] = (idx0 + k < N) ? g_cursor[idx0 + k] : 0;
    int tsum = c[0] + c[1] + c[2] + c[3];

    int v = tsum;
#pragma unroll
    for (int o = 1; o < 32; o <<= 1) {
        int xx = __shfl_up_sync(0xffffffffu, v, o);
        if (lane >= o) v += xx;
    }
    if (lane == 31) wsum[wid] = v;
    __syncthreads();

    if (t == 0) {
        int run = 0;
#pragma unroll
        for (int i = 0; i < 8; ++i) { int w = wsum[i]; wsum[i] = run; run += w; }
        atomicExch(&g_scanstate[b], (unsigned)(run + 1));  // publish (+1)
    }
    __syncthreads();

    if (wid == 0) {
        int ex = 0;
        for (int w0 = 0; w0 < b; w0 += 32) {
            int j = w0 + lane;
            int val = 0;
            if (j < b) {
                unsigned st;
                while ((st = atomicAdd(&g_scanstate[j], 0u)) == 0u)
                    __nanosleep(64);
                val = (int)st - 1;
            }
#pragma unroll
            for (int o = 16; o; o >>= 1)
                val += __shfl_xor_sync(0xffffffffu, val, o);
            ex += val;
        }
        if (lane == 0) s_ex = ex;
    }
    __syncthreads();

    int texcl = (v - tsum) + wsum[wid];
    int run = s_ex + texcl;
#pragma unroll
    for (int k = 0; k < 4; ++k) {
        int idx = idx0 + k;
        if (idx < N) {
            g_rowstart[idx] = run;
            g_cursor[idx]   = run;
            run += c[k];
            if (idx == N - 1) g_rowstart[N] = run;
        }
    }
}

// ===========================================================================
// K2: MERGED LayerNorm+ReLU (blocks [0, lnblocks)) and CSR fill (rest).
// ===========================================================================
__global__ void k_ln_fill(const float* __restrict__ x,
                          const float* __restrict__ gamma,
                          const float* __restrict__ beta,
                          const void* ei_, int N, int E, int lnblocks) {
    if ((int)blockIdx.x < lnblocks) {
        int w    = (blockIdx.x * blockDim.x + threadIdx.x) >> 5;
        int lane = threadIdx.x & 31;
        if (w >= N) return;

        float4 v = ((const float4*)x)[(size_t)w * 32 + lane];
        float s  = v.x + v.y + v.z + v.w;
        float sq = v.x * v.x + v.y * v.y + v.z * v.z + v.w * v.w;
#pragma unroll
        for (int o = 16; o; o >>= 1) {
            s  += __shfl_xor_sync(0xffffffffu, s, o);
            sq += __shfl_xor_sync(0xffffffffu, sq, o);
        }
        float mu  = s * (1.0f / C);
        float var = sq * (1.0f / C) - mu * mu;
        float rs  = rsqrtf(var + LN_EPS);

        float4 g = ((const float4*)gamma)[lane];
        float4 b = ((const float4*)beta)[lane];
        float hx = fmaxf(0.0f, (v.x - mu) * rs * g.x + b.x);
        float hy = fmaxf(0.0f, (v.y - mu) * rs * g.y + b.y);
        float hz = fmaxf(0.0f, (v.z - mu) * rs * g.z + b.z);
        float hw = fmaxf(0.0f, (v.w - mu) * rs * g.w + b.w);

        __half2 p0 = __floats2half2_rn(hx, hy);
        __half2 p1 = __floats2half2_rn(hz, hw);
        uint2 pk = make_uint2(*(uint32_t*)&p0, *(uint32_t*)&p1);
        ((uint2*)g_hh)[(size_t)w * 32 + lane] = pk;
    } else {
        bool i64 = is_i64(ei_, N, E);
        int e0 = ((blockIdx.x - lnblocks) * blockDim.x + threadIdx.x) * 2;
        if (e0 >= E) return;
        if (i64) {
            const long long* ei = (const long long*)ei_;
            if (e0 + 1 < E) {
                longlong2 sp = *(const longlong2*)(ei + e0);
                longlong2 dp = *(const longlong2*)(ei + E + e0);
                int p0 = atomicAdd(&g_cursor[(int)dp.x], 1);
                int p1 = atomicAdd(&g_cursor[(int)dp.y], 1);
                g_csr[p0] = (int)sp.x;
                g_csr[p1] = (int)sp.y;
            } else {
                int s = (int)ei[e0], d = (int)ei[(size_t)E + e0];
                g_csr[atomicAdd(&g_cursor[d], 1)] = s;
            }
        } else {
            const int* ei = (const int*)ei_;
            if (e0 + 1 < E) {
                int2 sp = *(const int2*)(ei + e0);
                int2 dp = *(const int2*)(ei + E + e0);
                int p0 = atomicAdd(&g_cursor[dp.x], 1);
                int p1 = atomicAdd(&g_cursor[dp.y], 1);
                g_csr[p0] = sp.x;
                g_csr[p1] = sp.y;
            } else {
                int s = ei[e0], d = ei[(size_t)E + e0];
                g_csr[atomicAdd(&g_cursor[d], 1)] = s;
            }
        }
    }
}

// ===========================================================================
// K3: gather-sum aggregation, one warp per dst node (EXACT R11 version:
// 49us, 32 regs, 80% occ — proven optimum after 3 failed variants).
// ===========================================================================
__global__ void k_agg(int N) {
    int w    = (blockIdx.x * blockDim.x + threadIdx.x) >> 5;
    int lane = threadIdx.x & 31;
    if (w >= N) return;

    int start = g_rowstart[w];
    int end   = g_rowstart[w + 1];
    int deg   = end - start;

    float4 acc = make_float4(0.f, 0.f, 0.f, 0.f);
    const uint2* hh = (const uint2*)g_hh;
    for (int base = start; base < end; base += 32) {
        int m = end - base; if (m > 32) m = 32;
        int s = (lane < m) ? g_csr[base + lane] : 0;
#pragma unroll 8
        for (int j = 0; j < 32; ++j) {
            if (j >= m) break;
            int sj = __shfl_sync(0xffffffffu, s, j);
            uint2 pk = hh[(size_t)sj * 32 + lane];
            float2 f0 = __half22float2(*(__half2*)&pk.x);
            float2 f1 = __half22float2(*(__half2*)&pk.y);
            acc.x += f0.x; acc.y += f0.y; acc.z += f1.x; acc.w += f1.y;
        }
    }
    float inv = deg > 0 ? 1.0f / (float)deg : 0.0f;
    __half2 p0 = __floats2half2_rn(acc.x * inv, acc.y * inv);
    __half2 p1 = __floats2half2_rn(acc.z * inv, acc.w * inv);
    ((uint2*)g_meanh)[(size_t)w * 32 + lane] =
        make_uint2(*(uint32_t*)&p0, *(uint32_t*)&p1);

    if (lane == 0) g_cursor[w] = 0;   // restore invariant for next replay
}

// ===========================================================================
// fp16 mma helper (m16n8k16, fp32 accumulate — plain sm_103 PTX, sm_80+)
// ===========================================================================
__device__ __forceinline__ void mma_f16(float4& d,
                                        uint32_t a0, uint32_t a1,
                                        uint32_t a2, uint32_t a3,
                                        uint32_t b0, uint32_t b1) {
    asm volatile(
        "mma.sync.aligned.m16n8k16.row.col.f32.f16.f16.f32 "
        "{%0,%1,%2,%3}, {%4,%5,%6,%7}, {%8,%9}, {%0,%1,%2,%3};"
        : "+f"(d.x), "+f"(d.y), "+f"(d.z), "+f"(d.w)
        : "r"(a0), "r"(a1), "r"(a2), "r"(a3), "r"(b0), "r"(b1));
}

// ldmatrix x4: 4 8x8 b16 matrices; lanes 0-7/8-15/16-23/24-31 give row addrs
// for matrices 0/1/2/3; result frags match mma operand layout by design.
#define LDMATRIX_X4(r0, r1, r2, r3, addr)                                    \
    asm volatile("ldmatrix.sync.aligned.m8n8.x4.shared.b16 "                 \
                 "{%0,%1,%2,%3}, [%4];"                                      \
                 : "=r"(r0), "=r"(r1), "=r"(r2), "=r"(r3) : "r"(addr))

// ===========================================================================
// K4: fp16 tensor-core GEMM via mma.sync m16n8k16 + ldmatrix.x4 fragments.
//   out[128-row tile, 128] = mean @ Wl^T + h @ Wr^T + bias + x
// Per ks: 1 A-ldmatrix + 8 B-ldmatrix + 16 mma (was 36 LDS + 16 mma).
// Pitches 272B/528B -> row-bank offset 4 -> each ldmatrix covers all 32
// banks exactly once (conflict-free). ~103KB SMEM -> 2 CTAs/SM.
// ===========================================================================
#define BPITCH_H 264
#define APITCH_H 136
#define OFFH_B   0
#define OFFH_A   (128 * BPITCH_H)               // halves
#define OFFH_BI  (OFFH_A + 128 * APITCH_H)      // halves (bias fp32 region)
#define SMEM_HALVES (OFFH_BI + 256)
#define SMEM_TOT (SMEM_HALVES * 2)

__global__ void __launch_bounds__(256, 2)
k_gemm_mma(const float* __restrict__ x,
           const float* __restrict__ Wl,
           const float* __restrict__ bl,
           const float* __restrict__ Wr,
           float* __restrict__ out, int N, int ntiles) {
    extern __shared__ __half smemh[];
    __half* sB  = smemh + OFFH_B;
    __half* sA  = smemh + OFFH_A;
    float*  sbi = (float*)(smemh + OFFH_BI);

    int tid  = threadIdx.x;
    int wid  = tid >> 5;
    int lane = tid & 31;
    int ly   = lane >> 2;   // groupID 0..7
    int lx   = lane & 3;    // threadID_in_group 0..3

    for (int i = tid; i < 128 * 128; i += 256) {
        int n = i >> 7, k = i & 127;
        sB[n * BPITCH_H + k]       = __float2half(Wl[i]);
        sB[n * BPITCH_H + 128 + k] = __float2half(Wr[i]);
    }
    for (int i = tid; i < 128; i += 256) sbi[i] = bl[i];
    __syncthreads();

    const uint4* meanp = (const uint4*)g_meanh;
    const uint4* hp    = (const uint4*)g_hh;
    uint4* sA4 = (uint4*)sA;

    int rb = wid * 16;

    // ldmatrix lane-address bases (byte offsets into smem, 32-bit addresses)
    uint32_t sA_u = (uint32_t)__cvta_generic_to_shared(sA);
    uint32_t sB_u = (uint32_t)__cvta_generic_to_shared(sB);
    int lane7 = lane & 7;
    int bit3  = (lane >> 3) & 1;
    int bit4  = (lane >> 4) & 1;
    // A: matrices (row lo/hi) x (k lo/hi): M0=lanes0-7,(r,kl) M1=(r+8,kl)
    //    M2=(r,kh) M3=(r+8,kh)  -> r0..r3 = a0..a3
    uint32_t a_base = sA_u
        + (uint32_t)((rb + lane7 + 8 * bit3) * (APITCH_H * 2) + 16 * bit4);
    // B: M0=(n lo,k lo) M1=(n lo,k hi) M2=(n+8,k lo) M3=(n+8,k hi)
    //    -> r0,r1 = b0,b1 of n-tile 2p; r2,r3 = b0,b1 of n-tile 2p+1
    uint32_t b_base = sB_u
        + (uint32_t)((lane7 + 8 * bit4) * (BPITCH_H * 2) + 16 * bit3);

    for (int t = blockIdx.x; t < ntiles; t += gridDim.x) {
        int rbase = t * 128;
        float4 acc[16];
#pragma unroll
        for (int nt = 0; nt < 16; ++nt) acc[nt] = make_float4(0.f, 0.f, 0.f, 0.f);

#pragma unroll
        for (int half = 0; half < 2; ++half) {
            const uint4* src = half ? hp : meanp;
            for (int i = tid; i < 128 * 16; i += 256) {
                int r = i >> 4, c8 = i & 15;
                int row = rbase + r;
                uint4 pk = (row < N) ? src[(size_t)row * 16 + c8]
                                     : make_uint4(0u, 0u, 0u, 0u);
                sA4[r * 17 + c8] = pk;
            }
            __syncthreads();

            uint32_t kbaseB = (uint32_t)(half * 256);   // 128 halves in bytes
#pragma unroll
            for (int ks = 0; ks < 8; ++ks) {
                uint32_t koff = (uint32_t)(ks * 32);    // 16 halves in bytes
                uint32_t a0, a1, a2, a3;
                LDMATRIX_X4(a0, a1, a2, a3, a_base + koff);
#pragma unroll
                for (int p = 0; p < 8; ++p) {
                    uint32_t b0, b1, b2, b3;
                    uint32_t baddr = b_base
                        + (uint32_t)(p * 16 * (BPITCH_H * 2)) + kbaseB + koff;
                    LDMATRIX_X4(b0, b1, b2, b3, baddr);
                    mma_f16(acc[2 * p],     a0, a1, a2, a3, b0, b1);
                    mma_f16(acc[2 * p + 1], a0, a1, a2, a3, b2, b3);
                }
            }
            __syncthreads();
        }

        int row0 = rbase + rb + ly;
        int row1 = row0 + 8;
#pragma unroll
        for (int nt = 0; nt < 16; ++nt) {
            int col = nt * 8 + lx * 2;
            float2 bv = *(const float2*)(sbi + col);
            if (row0 < N) {
                float2 xv = ((const float2*)x)[(size_t)row0 * 64 + (col >> 1)];
                float2 o = make_float2(acc[nt].x + bv.x + xv.x,
                                       acc[nt].y + bv.y + xv.y);
                ((float2*)out)[(size_t)row0 * 64 + (col >> 1)] = o;
            }
            if (row1 < N) {
                float2 xv = ((const float2*)x)[(size_t)row1 * 64 + (col >> 1)];
                float2 o = make_float2(acc[nt].z + bv.x + xv.x,
                                       acc[nt].w + bv.y + xv.y);
                ((float2*)out)[(size_t)row1 * 64 + (col >> 1)] = o;
            }
        }
    }
}

// ===========================================================================
extern "C" void kernel_launch(void* const* d_in, const int* in_sizes, int n_in,
                              void* d_out, int out_size) {
    const float* x     = (const float*)d_in[0];
    const void*  ei    = d_in[1];
    const float* gamma = (const float*)d_in[2];
    const float* beta  = (const float*)d_in[3];
    const float* Wl    = (const float*)d_in[4];
    const float* bl    = (const float*)d_in[5];
    const float* Wr    = (const float*)d_in[6];
    float*       out   = (float*)d_out;

    int N = in_sizes[0] / C;       // 100000
    int E = in_sizes[1] / 2;       // 1600000
    int nb = (N + 1023) / 1024;    // 98 — co-resident, single-pass scan OK
    int ntiles = (N + 127) / 128;

    int lnblocks   = (N + 7) / 8;            // 12500
    int fillblocks = (E / 2 + 255) / 256;    // 3125

    k_hist<<<(E + 255) / 256, 256>>>(ei, N, E);                                    // 0
    k_scan<<<nb, 256>>>(N, nb);                                                    // 1
    k_ln_fill<<<lnblocks + fillblocks, 256>>>(x, gamma, beta, ei, N, E, lnblocks); // 2
    k_agg<<<(N + 7) / 8, 256>>>(N);                                                // 3
    cudaFuncSetAttribute(k_gemm_mma, cudaFuncAttributeMaxDynamicSharedMemorySize,
                         SMEM_TOT);
    int sms = 148;
    cudaDeviceGetAttribute(&sms, cudaDevAttrMultiProcessorCount, 0);
    int grid = 2 * sms < ntiles ? 2 * sms : ntiles;
    k_gemm_mma<<<grid, 256, SMEM_TOT>>>(x, Wl, bl, Wr, out, N, ntiles);            // 4
}